// round 17
// baseline (speedup 1.0000x reference)
#include <cuda_runtime.h>
#include <math.h>

#define B_  4
#define S_  2048
#define HID 1024
#define NH  16
#define HD  64

typedef unsigned long long u64;
typedef unsigned int u32;

// Scratch (device globals: no allocation allowed in kernel_launch).
__device__ __align__(128) float g_Q[B_ * NH * S_ * HD];
__device__ __align__(128) float g_K[B_ * NH * S_ * HD];
__device__ __align__(128) float g_V[B_ * NH * S_ * HD];

// ---- tf32 / mma helpers ---------------------------------------------------
__device__ __forceinline__ u32 tf32r(float f) {
    u32 r; asm("cvt.rna.tf32.f32 %0, %1;" : "=r"(r) : "f"(f)); return r;
}
__device__ __forceinline__ void split2(float v, u32& hi, u32& lo) {
    hi = tf32r(v);
    lo = tf32r(v - __uint_as_float(hi));
}
__device__ __forceinline__ void mma_tf32(float* c, u32 a0, u32 a1, u32 a2,
                                         u32 a3, u32 b0, u32 b1) {
    asm("mma.sync.aligned.m16n8k8.row.col.f32.tf32.tf32.f32 "
        "{%0,%1,%2,%3}, {%4,%5,%6,%7}, {%8,%9}, {%0,%1,%2,%3};"
        : "+f"(c[0]), "+f"(c[1]), "+f"(c[2]), "+f"(c[3])
        : "r"(a0), "r"(a1), "r"(a2), "r"(a3), "r"(b0), "r"(b1));
}

// ---------------------------------------------------------------------------
// Kernel 1: tf32 HMMA projection GEMM (EXACT Round-11 version, proven 2455).
// ---------------------------------------------------------------------------
#define XP 68
#define WP 136

__global__ __launch_bounds__(256, 2) void qkv_gemm_tc(
    const float* __restrict__ x,
    const float* __restrict__ Wq, const float* __restrict__ bq,
    const float* __restrict__ Wk, const float* __restrict__ bk,
    const float* __restrict__ Wv, const float* __restrict__ bv)
{
    extern __shared__ float smg[];
    float* xs = smg;
    float* ws = smg + 128 * XP;

    const int z = blockIdx.z;
    const float* W    = (z == 0) ? Wq : (z == 1) ? Wk : Wv;
    const float* bias = (z == 0) ? bq : (z == 1) ? bk : bv;
    float* dst        = (z == 0) ? g_Q : (z == 1) ? g_K : g_V;

    const int n0 = blockIdx.x * 128;
    const int m0 = blockIdx.y * 128;
    const int tid = threadIdx.x;
    const int lane = tid & 31;
    const int wid = tid >> 5;
    const int wm = wid & 1;
    const int wn = wid >> 1;
    const int gr = lane >> 2;
    const int gc = lane & 3;

    float acc[4][4][4] = {};

    for (int k0 = 0; k0 < HID; k0 += 64) {
        __syncthreads();
        #pragma unroll
        for (int i = 0; i < 8; i++) {
            int lin = tid + i * 256;
            int r = lin >> 4, c = lin & 15;
            float4 xv = *(const float4*)&x[(size_t)(m0 + r) * HID + k0 + c * 4];
            xs[r * XP + c * 4 + 0] = xv.x;
            xs[r * XP + c * 4 + 1] = xv.y;
            xs[r * XP + c * 4 + 2] = xv.z;
            xs[r * XP + c * 4 + 3] = xv.w;
            int rw = lin >> 5, cw = lin & 31;
            float4 wv = *(const float4*)&W[(size_t)(k0 + rw) * HID + n0 + cw * 4];
            *(float4*)&ws[rw * WP + cw * 4] = wv;
        }
        __syncthreads();

        #pragma unroll
        for (int ks = 0; ks < 8; ks++) {
            const int kk = ks * 8;
            u32 bh[4][2], bl[4][2];
            #pragma unroll
            for (int tn = 0; tn < 4; tn++) {
                int ccol = wn * 32 + tn * 8 + gr;
                split2(ws[(kk + gc)     * WP + ccol], bh[tn][0], bl[tn][0]);
                split2(ws[(kk + gc + 4) * WP + ccol], bh[tn][1], bl[tn][1]);
            }
            #pragma unroll
            for (int tm = 0; tm < 4; tm++) {
                int r = wm * 64 + tm * 16 + gr;
                u32 ah[4], al[4];
                split2(xs[(r)     * XP + kk + gc],     ah[0], al[0]);
                split2(xs[(r + 8) * XP + kk + gc],     ah[1], al[1]);
                split2(xs[(r)     * XP + kk + gc + 4], ah[2], al[2]);
                split2(xs[(r + 8) * XP + kk + gc + 4], ah[3], al[3]);
                #pragma unroll
                for (int tn = 0; tn < 4; tn++) {
                    float* c = acc[tm][tn];
                    mma_tf32(c, ah[0], ah[1], ah[2], ah[3],
                             bh[tn][0], bh[tn][1]);
                    mma_tf32(c, ah[0], ah[1], ah[2], ah[3],
                             bl[tn][0], bl[tn][1]);
                    mma_tf32(c, al[0], al[1], al[2], al[3],
                             bh[tn][0], bh[tn][1]);
                }
            }
        }
    }

    #pragma unroll
    for (int tm = 0; tm < 4; tm++) {
        #pragma unroll
        for (int half = 0; half < 2; half++) {
            int m = m0 + wm * 64 + tm * 16 + gr + half * 8;
            int b = m >> 11;
            int s = m & (S_ - 1);
            #pragma unroll
            for (int tn = 0; tn < 4; tn++) {
                int n = n0 + wn * 32 + tn * 8 + 2 * gc;
                float2 bb = *(const float2*)&bias[n];
                float2 r;
                r.x = acc[tm][tn][half * 2 + 0] + bb.x;
                r.y = acc[tm][tn][half * 2 + 1] + bb.y;
                int h = n >> 6, d = n & 63;
                *(float2*)&dst[(((size_t)b * NH + h) * S_ + s) * HD + d] = r;
            }
        }
    }
}

// ---------------------------------------------------------------------------
// Kernel 2: HMMA flash attention, 512 threads / 16 warps.
// S = Q·K^T natural orientation; fixed-max softmax; P as tf32 u32 [q][k]
// stride 132 (k goes to 127 — stride MUST exceed 128; R14/R16 bug class).
// Warp grid: scores 4qm x 4kn (32q x 32k); PV 4qm x 4dn (32q x 16d).
// ---------------------------------------------------------------------------
// smem offsets (bytes)
#define A_QS  0                          // f32 [128][68]  = 34816
#define A_KS  34816                      // f32 [128][68]  = 34816
#define A_VS  (34816 * 2)                // f32 [128][72]  = 36864
#define A_PS  (34816 * 2 + 36864)        // u32 [128][132] = 67584
#define A_LSM (34816 * 2 + 36864 + 67584)  // f32 [128][4] = 2048
#define A_TOT (A_LSM + 2048)             // 176128

__global__ __launch_bounds__(512, 1) void attn_kernel(
    const float* __restrict__ T,
    const int*   __restrict__ mask,
    const float* __restrict__ alpha_p,
    float*       __restrict__ out)
{
    extern __shared__ char sma[];
    float* Qs  = (float*)(sma + A_QS);   // [q][d], stride 68
    float* Ks  = (float*)(sma + A_KS);   // [k][d], stride 68
    float* Vs  = (float*)(sma + A_VS);   // [k][d], stride 72
    u32*   Ps  = (u32*)(sma + A_PS);     // [q][k] tf32 bits, stride 132
    float* Lsm = (float*)(sma + A_LSM);  // [q][4] per-kn partials

    const int h  = blockIdx.x;           // head fastest: T/mask L2 reuse
    const int q0 = blockIdx.y * 128;
    const int b  = blockIdx.z;
    const int tid = threadIdx.x;
    const int lane = tid & 31;
    const int wid = tid >> 5;            // 0..15
    const int qm = wid >> 2;             // q-quarter (both phases)
    const int kn = wid & 3;              // k-quarter (scores) / d-quarter (PV)
    const int gr = lane >> 2;
    const int gc = lane & 3;

    const float nalpha = -fabsf(*alpha_p);
    const float* Qg = g_Q + ((size_t)b * NH + h) * S_ * HD;
    const float* Kg = g_K + ((size_t)b * NH + h) * S_ * HD;
    const float* Vg = g_V + ((size_t)b * NH + h) * S_ * HD;
    const float* Tb = T    + (size_t)b * S_ * S_;
    const int*   Mb = mask + (size_t)b * S_ * S_;

    // Q -> Qs[q][d] natural (no transpose)
    #pragma unroll
    for (int i = 0; i < 4; i++) {
        int lin = tid + i * 512;
        int q = lin >> 4, c = lin & 15;
        float4 v = *(const float4*)&Qg[(size_t)(q0 + q) * HD + c * 4];
        *(float4*)&Qs[q * 68 + c * 4] = v;
    }

    float oacc[2][2][4] = {};   // [tm(q)][tn2(d)][c]
    float l_part[4] = {};       // q-slots: tm*2 + hh

    for (int kt = 0; kt < 16; kt++) {
        const int k0 = kt * 128;

        __syncthreads();   // prior-tile Ks/Vs/Ps reads done (covers Qs @0)
        #pragma unroll
        for (int i = 0; i < 4; i++) {
            int lin = tid + i * 512;
            int k = lin >> 4, c = lin & 15;
            float4 kv = *(const float4*)&Kg[(size_t)(k0 + k) * HD + c * 4];
            *(float4*)&Ks[k * 68 + c * 4] = kv;
            float4 vv = *(const float4*)&Vg[(size_t)(k0 + k) * HD + c * 4];
            *(float4*)&Vs[k * 72 + c * 4] = vv;
        }
        __syncthreads();

        // ---- scores: S = Q·K^T, 3-pass tf32. C rows = q, cols = k ----
        float sacc[2][4][4] = {};
        #pragma unroll
        for (int ks = 0; ks < 8; ks++) {
            const int kk = ks * 8;    // d-chunk
            u32 bh[4][2], bl[4][2];
            #pragma unroll
            for (int tn = 0; tn < 4; tn++) {
                int kcol = kn * 32 + tn * 8 + gr;       // key index (n)
                split2(Ks[kcol * 68 + kk + gc],     bh[tn][0], bl[tn][0]);
                split2(Ks[kcol * 68 + kk + gc + 4], bh[tn][1], bl[tn][1]);
            }
            #pragma unroll
            for (int tm = 0; tm < 2; tm++) {
                int r = qm * 32 + tm * 16 + gr;         // query row (m)
                u32 ah[4], al[4];
                split2(Qs[(r)     * 68 + kk + gc],     ah[0], al[0]);
                split2(Qs[(r + 8) * 68 + kk + gc],     ah[1], al[1]);
                split2(Qs[(r)     * 68 + kk + gc + 4], ah[2], al[2]);
                split2(Qs[(r + 8) * 68 + kk + gc + 4], ah[3], al[3]);
                #pragma unroll
                for (int tn = 0; tn < 4; tn++) {
                    float* c = sacc[tm][tn];
                    mma_tf32(c, ah[0], ah[1], ah[2], ah[3],
                             bh[tn][0], bh[tn][1]);
                    mma_tf32(c, ah[0], ah[1], ah[2], ah[3],
                             bl[tn][0], bl[tn][1]);
                    mma_tf32(c, al[0], al[1], al[2], al[3],
                             bh[tn][0], bh[tn][1]);
                }
            }
        }

        // ---- fixed-max softmax + tf32 P store. C: (q=row, k=col) ----
        #pragma unroll
        for (int tm = 0; tm < 2; tm++) {
            #pragma unroll
            for (int hh = 0; hh < 2; hh++) {
                int q_local = qm * 32 + tm * 16 + gr + hh * 8;
                int qg = q0 + q_local;
                float lsum = l_part[tm * 2 + hh];
                #pragma unroll
                for (int tn = 0; tn < 4; tn++) {
                    int k_local = kn * 32 + tn * 8 + 2 * gc;
                    size_t off = (size_t)qg * S_ + k0 + k_local;
                    float2 t2 = *(const float2*)&Tb[off];
                    int2  m2  = *(const int2*)  &Mb[off];
                    float s0 = sacc[tm][tn][hh * 2 + 0];
                    float s1 = sacc[tm][tn][hh * 2 + 1];
                    float v0 = (m2.x == 0) ? -1e9f : s0 * 0.125f + nalpha * t2.x;
                    float v1 = (m2.y == 0) ? -1e9f : s1 * 0.125f + nalpha * t2.y;
                    u32 p0 = tf32r(__expf(v0 - 10.0f));
                    u32 p1 = tf32r(__expf(v1 - 10.0f));
                    lsum += __uint_as_float(p0) + __uint_as_float(p1);
                    Ps[q_local * 132 + k_local]     = p0;
                    Ps[q_local * 132 + k_local + 1] = p1;
                }
                l_part[tm * 2 + hh] = lsum;
            }
        }
        __syncthreads();   // Ps visible to all warps

        // ---- PV: O += P·V, 2-pass (P tf32, V hi/lo). C rows = q, cols = d --
        #pragma unroll
        for (int ks = 0; ks < 16; ks++) {
            const int kk = ks * 8;    // k-chunk
            u32 vbh[2][2], vbl[2][2];
            #pragma unroll
            for (int tn2 = 0; tn2 < 2; tn2++) {
                int dcol = kn * 16 + tn2 * 8 + gr;
                split2(Vs[(kk + gc)     * 72 + dcol], vbh[tn2][0], vbl[tn2][0]);
                split2(Vs[(kk + gc + 4) * 72 + dcol], vbh[tn2][1], vbl[tn2][1]);
            }
            #pragma unroll
            for (int tm = 0; tm < 2; tm++) {
                int r = qm * 32 + tm * 16 + gr;
                u32 p0 = Ps[(r)     * 132 + kk + gc];
                u32 p1 = Ps[(r + 8) * 132 + kk + gc];
                u32 p2 = Ps[(r)     * 132 + kk + gc + 4];
                u32 p3 = Ps[(r + 8) * 132 + kk + gc + 4];
                #pragma unroll
                for (int tn2 = 0; tn2 < 2; tn2++) {
                    float* c = oacc[tm][tn2];
                    mma_tf32(c, p0, p1, p2, p3, vbh[tn2][0], vbh[tn2][1]);
                    mma_tf32(c, p0, p1, p2, p3, vbl[tn2][0], vbl[tn2][1]);
                }
            }
        }
    }

    // ---- l reduction: xor over gc lanes, then per-kn slot in smem ----
    #pragma unroll
    for (int i = 0; i < 4; i++) {
        l_part[i] += __shfl_xor_sync(0xFFFFFFFFu, l_part[i], 1);
        l_part[i] += __shfl_xor_sync(0xFFFFFFFFu, l_part[i], 2);
    }
    if (gc == 0) {
        #pragma unroll
        for (int tm = 0; tm < 2; tm++)
            #pragma unroll
            for (int hh = 0; hh < 2; hh++) {
                int q = qm * 32 + tm * 16 + gr + hh * 8;
                Lsm[q * 4 + kn] = l_part[tm * 2 + hh];
            }
    }
    __syncthreads();

    // ---- epilogue: out = O / l ----
    #pragma unroll
    for (int tm = 0; tm < 2; tm++) {
        #pragma unroll
        for (int hh = 0; hh < 2; hh++) {
            int row = qm * 32 + tm * 16 + gr + hh * 8;
            float inv = 1.0f / (Lsm[row * 4] + Lsm[row * 4 + 1]
                              + Lsm[row * 4 + 2] + Lsm[row * 4 + 3]);
            int s = q0 + row;
            #pragma unroll
            for (int tn2 = 0; tn2 < 2; tn2++) {
                int d = kn * 16 + tn2 * 8 + 2 * gc;
                float2 o;
                o.x = oacc[tm][tn2][hh * 2 + 0] * inv;
                o.y = oacc[tm][tn2][hh * 2 + 1] * inv;
                *(float2*)&out[((size_t)b * S_ + s) * HID + h * HD + d] = o;
            }
        }
    }
}

// ---------------------------------------------------------------------------
// Launch
// ---------------------------------------------------------------------------
extern "C" void kernel_launch(void* const* d_in, const int* in_sizes, int n_in,
                              void* d_out, int out_size)
{
    const float* x     = (const float*)d_in[0];
    const float* T     = (const float*)d_in[1];
    const int*   mask  = (const int*)  d_in[2];
    const float* Wq    = (const float*)d_in[3];
    const float* bq    = (const float*)d_in[4];
    const float* Wk    = (const float*)d_in[5];
    const float* bk    = (const float*)d_in[6];
    const float* Wv    = (const float*)d_in[7];
    const float* bv    = (const float*)d_in[8];
    const float* alpha = (const float*)d_in[9];
    float* out = (float*)d_out;

    const int smem_g = (128 * XP + 64 * WP) * (int)sizeof(float);   // 69632
    cudaFuncSetAttribute(qkv_gemm_tc,
                         cudaFuncAttributeMaxDynamicSharedMemorySize, smem_g);
    dim3 g1(HID / 128, (B_ * S_) / 128, 3);
    qkv_gemm_tc<<<g1, 256, smem_g>>>(x, Wq, bq, Wk, bk, Wv, bv);

    cudaFuncSetAttribute(attn_kernel,
                         cudaFuncAttributeMaxDynamicSharedMemorySize, A_TOT);
    dim3 g2(NH, S_ / 128, B_);
    attn_kernel<<<g2, 512, A_TOT>>>(T, mask, alpha, out);
}